// round 1
// baseline (speedup 1.0000x reference)
#include <cuda_runtime.h>
#include <math.h>

#define SEQ  2048
#define HID  2048
#define NH   16
#define HD   128
#define RD   64
#define DT   192        // HD + RD
#define KVC  512
#define QC   1024

// ---------------- scratch (device globals: allocation-free) ----------------
__device__ float g_kvc[SEQ * KVC];
__device__ float g_qc [SEQ * QC];
__device__ float g_K  [SEQ * NH * DT];
__device__ float g_Q  [SEQ * NH * DT];
__device__ float g_V  [SEQ * NH * HD];
__device__ float g_ctx[SEQ * NH * HD];

// ---------------------------------------------------------------------------
// GEMM: C[M,N] = A[M,K] @ B[N,K]^T + bias    (both row-major, K contiguous)
// 128x128 tile, kt=16, 256 threads, 8x8 per thread, register double-buffer.
// EPI: 0 = plain row-major store to C (ld = N)
//      1 = split store to [s][h][192] at offset 0   (N must be 2048)
//      2 = RoPE (head-indexed) store to [s][h][192] at offset 128 (N = 1024)
// ---------------------------------------------------------------------------
template<int EPI>
__global__ void __launch_bounds__(256, 2)
gemm_nt(const float* __restrict__ A, const float* __restrict__ B,
        const float* __restrict__ bias, float* __restrict__ C,
        int N, int K)
{
    __shared__ float As[16][128];
    __shared__ float Bs[16][128];

    const int tid = threadIdx.x;
    const int bm  = blockIdx.y * 128;
    const int bn  = blockIdx.x * 128;
    const int ty  = tid >> 4;      // 0..15 -> 8 rows each
    const int tx  = tid & 15;      // 0..15 -> 8 cols each

    // Loader: threads 0..127 own one A row, 128..255 one B row.
    // Each loads 64B contiguous (4 x float4) per k-tile -> full sectors,
    // transposed STS hits distinct banks (bank = row % 32).
    const int   lrow = tid & 127;
    const float* src = (tid < 128) ? (A + (size_t)(bm + lrow) * K)
                                   : (B + (size_t)(bn + lrow) * K);
    float* dstS = (tid < 128) ? &As[0][lrow] : &Bs[0][lrow];

    float4 st[4];
#pragma unroll
    for (int t = 0; t < 4; t++) st[t] = *(const float4*)(src + t * 4);

    float acc[8][8];
#pragma unroll
    for (int i = 0; i < 8; i++)
#pragma unroll
        for (int j = 0; j < 8; j++) acc[i][j] = 0.f;

    for (int k0 = 0; k0 < K; k0 += 16) {
#pragma unroll
        for (int t = 0; t < 4; t++) {
            dstS[(t * 4 + 0) * 128] = st[t].x;
            dstS[(t * 4 + 1) * 128] = st[t].y;
            dstS[(t * 4 + 2) * 128] = st[t].z;
            dstS[(t * 4 + 3) * 128] = st[t].w;
        }
        __syncthreads();
        if (k0 + 16 < K) {
#pragma unroll
            for (int t = 0; t < 4; t++)
                st[t] = *(const float4*)(src + k0 + 16 + t * 4);
        }
#pragma unroll
        for (int k = 0; k < 16; k++) {
            float a[8], b[8];
            *(float4*)&a[0] = *(const float4*)&As[k][ty * 8];
            *(float4*)&a[4] = *(const float4*)&As[k][ty * 8 + 4];
            *(float4*)&b[0] = *(const float4*)&Bs[k][tx * 8];
            *(float4*)&b[4] = *(const float4*)&Bs[k][tx * 8 + 4];
#pragma unroll
            for (int i = 0; i < 8; i++)
#pragma unroll
                for (int j = 0; j < 8; j++)
                    acc[i][j] = fmaf(a[i], b[j], acc[i][j]);
        }
        __syncthreads();
    }

    // ---------------- epilogue ----------------
    const int o0 = bn + tx * 8;

    float sn[4], cs[4];
    if (EPI == 2) {
        const int hh  = o0 >> 6;
        const int rr  = o0 & 63;
#pragma unroll
        for (int jp = 0; jp < 4; jp++) {
            int jj = (rr >> 1) + jp;   // pair index within rope dim
            // inv_freq = 10000^(-2*jj/RD)
            float fr  = __expf(-((float)(2 * jj) * (1.0f / (float)RD)) * 9.210340371976184f);
            float ang = (float)hh * fr;   // positions = head index (faithful)
            sincosf(ang, &sn[jp], &cs[jp]);
        }
    }

#pragma unroll
    for (int i = 0; i < 8; i++) {
        const int r = bm + ty * 8 + i;
        float v[8];
        if (EPI == 2) {
            const int hh = o0 >> 6;
            const int rr = o0 & 63;
#pragma unroll
            for (int j = 0; j < 8; j += 2) {
                float x1 = acc[i][j]     + bias[o0 + j];
                float x2 = acc[i][j + 1] + bias[o0 + j + 1];
                int jp = j >> 1;
                v[j]     = x1 * cs[jp] - x2 * sn[jp];
                v[j + 1] = x1 * sn[jp] + x2 * cs[jp];
            }
            float* d = C + ((size_t)r * NH + hh) * DT + HD + rr;
            *(float4*)d       = make_float4(v[0], v[1], v[2], v[3]);
            *(float4*)(d + 4) = make_float4(v[4], v[5], v[6], v[7]);
        } else {
#pragma unroll
            for (int j = 0; j < 8; j++) v[j] = acc[i][j] + bias[o0 + j];
            float* d;
            if (EPI == 1)
                d = C + ((size_t)r * NH + (o0 >> 7)) * DT + (o0 & 127);
            else
                d = C + (size_t)r * N + o0;
            *(float4*)d       = make_float4(v[0], v[1], v[2], v[3]);
            *(float4*)(d + 4) = make_float4(v[4], v[5], v[6], v[7]);
        }
    }
}

// ---------------------------------------------------------------------------
// Flash attention, fp32. One block = (head, 64-query tile), 256 threads.
// Thread (ry=tid/16, cx=tid%16): owns 4 query rows (ry*4+i).
//   S-phase: 4x4 score tile (cols cx*4+j) against transposed Q/K smem.
//   PV-phase: ctx 4x8 (d-cols cx*4+j and 64+cx*4+j).
// Softmax stats replicated in registers across each 16-lane row group.
// ---------------------------------------------------------------------------
#define ATT_SM_FLOATS (DT * 64 * 2 + 64 * HD + 64 * 68)
#define ATT_SM_BYTES  (ATT_SM_FLOATS * 4)

__device__ __forceinline__ void store_t16(float* d, float4 v0, float4 v1,
                                          float4 v2, float4 v3)
{
    d[0 * 64] = v0.x;  d[1 * 64] = v0.y;  d[2 * 64] = v0.z;  d[3 * 64] = v0.w;
    d[4 * 64] = v1.x;  d[5 * 64] = v1.y;  d[6 * 64] = v1.z;  d[7 * 64] = v1.w;
    d[8 * 64] = v2.x;  d[9 * 64] = v2.y;  d[10 * 64] = v2.z; d[11 * 64] = v2.w;
    d[12 * 64] = v3.x; d[13 * 64] = v3.y; d[14 * 64] = v3.z; d[15 * 64] = v3.w;
}

__global__ void __launch_bounds__(256, 1)
attn_kernel(const float* __restrict__ Qg, const float* __restrict__ Kg,
            const float* __restrict__ Vg, float* __restrict__ ctxg)
{
    extern __shared__ float sm[];
    float* Qst = sm;                 // [192][64]  (k-major, transposed)
    float* Kst = Qst + DT * 64;      // [192][64]
    float* Vs  = Kst + DT * 64;      // [64][128]
    float* Ps  = Vs + 64 * HD;       // [64][68]   (padded)

    const int tid = threadIdx.x;
    const int h   = blockIdx.y;
    const int q0  = blockIdx.x * 64;
    const int ry  = tid >> 4;
    const int cx  = tid & 15;

    // ---- load Q tile, transposed: each lane takes 64B of one row ----
    {
        const float* base = Qg + h * DT;
#pragma unroll
        for (int lq = 0; lq < 3; lq++) {
            int c = tid + 256 * lq;          // 0..767
            int row = c & 63, seg = c >> 6;  // seg 0..11
            const float* p = base + (size_t)(q0 + row) * (NH * DT) + seg * 16;
            float4 v0 = *(const float4*)(p);
            float4 v1 = *(const float4*)(p + 4);
            float4 v2 = *(const float4*)(p + 8);
            float4 v3 = *(const float4*)(p + 12);
            store_t16(Qst + (seg * 16) * 64 + row, v0, v1, v2, v3);
        }
    }

    float m_[4], l_[4], ctx[4][8];
#pragma unroll
    for (int i = 0; i < 4; i++) {
        m_[i] = -1e30f; l_[i] = 0.f;
#pragma unroll
        for (int j = 0; j < 8; j++) ctx[i][j] = 0.f;
    }

    const float SCALE = 0.07216878364870323f;  // 1/sqrt(192)

    for (int kt = 0; kt < SEQ / 64; kt++) {
        const int kbase = kt * 64;
        // ---- K tile (transposed) ----
        {
            const float* base = Kg + h * DT;
#pragma unroll
            for (int lq = 0; lq < 3; lq++) {
                int c = tid + 256 * lq;
                int row = c & 63, seg = c >> 6;
                const float* p = base + (size_t)(kbase + row) * (NH * DT) + seg * 16;
                float4 v0 = *(const float4*)(p);
                float4 v1 = *(const float4*)(p + 4);
                float4 v2 = *(const float4*)(p + 8);
                float4 v3 = *(const float4*)(p + 12);
                store_t16(Kst + (seg * 16) * 64 + row, v0, v1, v2, v3);
            }
        }
        // ---- V tile (natural layout) ----
        {
            const float* base = Vg + h * HD;
#pragma unroll
            for (int lq = 0; lq < 8; lq++) {
                int c = tid + 256 * lq;
                int row = c >> 5, c4 = (c & 31) << 2;
                *(float4*)&Vs[row * HD + c4] =
                    *(const float4*)(base + (size_t)(kbase + row) * (NH * HD) + c4);
            }
        }
        __syncthreads();

        // ---- S = Q K^T (4x4 per thread) ----
        float s[4][4];
#pragma unroll
        for (int i = 0; i < 4; i++)
#pragma unroll
            for (int j = 0; j < 4; j++) s[i][j] = 0.f;

#pragma unroll 4
        for (int k = 0; k < DT; k++) {
            float4 a = *(const float4*)&Qst[k * 64 + ry * 4];
            float4 b = *(const float4*)&Kst[k * 64 + cx * 4];
            s[0][0] = fmaf(a.x, b.x, s[0][0]); s[0][1] = fmaf(a.x, b.y, s[0][1]);
            s[0][2] = fmaf(a.x, b.z, s[0][2]); s[0][3] = fmaf(a.x, b.w, s[0][3]);
            s[1][0] = fmaf(a.y, b.x, s[1][0]); s[1][1] = fmaf(a.y, b.y, s[1][1]);
            s[1][2] = fmaf(a.y, b.z, s[1][2]); s[1][3] = fmaf(a.y, b.w, s[1][3]);
            s[2][0] = fmaf(a.z, b.x, s[2][0]); s[2][1] = fmaf(a.z, b.y, s[2][1]);
            s[2][2] = fmaf(a.z, b.z, s[2][2]); s[2][3] = fmaf(a.z, b.w, s[2][3]);
            s[3][0] = fmaf(a.w, b.x, s[3][0]); s[3][1] = fmaf(a.w, b.y, s[3][1]);
            s[3][2] = fmaf(a.w, b.z, s[3][2]); s[3][3] = fmaf(a.w, b.w, s[3][3]);
        }
#pragma unroll
        for (int i = 0; i < 4; i++)
#pragma unroll
            for (int j = 0; j < 4; j++) s[i][j] *= SCALE;

        // ---- online softmax (row stats replicated over 16-lane groups) ----
        float tm[4];
#pragma unroll
        for (int i = 0; i < 4; i++)
            tm[i] = fmaxf(fmaxf(s[i][0], s[i][1]), fmaxf(s[i][2], s[i][3]));
#pragma unroll
        for (int off = 8; off >= 1; off >>= 1)
#pragma unroll
            for (int i = 0; i < 4; i++)
                tm[i] = fmaxf(tm[i], __shfl_xor_sync(0xffffffffu, tm[i], off, 16));

        float corr[4], rs[4];
#pragma unroll
        for (int i = 0; i < 4; i++) {
            float mn = fmaxf(m_[i], tm[i]);
            corr[i]  = __expf(m_[i] - mn);
            m_[i]    = mn;
            float r  = 0.f;
#pragma unroll
            for (int j = 0; j < 4; j++) {
                float p = __expf(s[i][j] - mn);
                s[i][j] = p;
                r += p;
            }
            rs[i] = r;
        }
#pragma unroll
        for (int off = 8; off >= 1; off >>= 1)
#pragma unroll
            for (int i = 0; i < 4; i++)
                rs[i] += __shfl_xor_sync(0xffffffffu, rs[i], off, 16);
#pragma unroll
        for (int i = 0; i < 4; i++) l_[i] = l_[i] * corr[i] + rs[i];

        // ---- stage P, rescale ctx ----
#pragma unroll
        for (int i = 0; i < 4; i++) {
            *(float4*)&Ps[(ry * 4 + i) * 68 + cx * 4] =
                make_float4(s[i][0], s[i][1], s[i][2], s[i][3]);
#pragma unroll
            for (int j = 0; j < 8; j++) ctx[i][j] *= corr[i];
        }
        __syncthreads();

        // ---- ctx += P @ V ----
#pragma unroll 2
        for (int kk = 0; kk < 64; kk++) {
            float4 v0 = *(const float4*)&Vs[kk * HD + cx * 4];
            float4 v1 = *(const float4*)&Vs[kk * HD + 64 + cx * 4];
#pragma unroll
            for (int i = 0; i < 4; i++) {
                float p = Ps[(ry * 4 + i) * 68 + kk];
                ctx[i][0] = fmaf(p, v0.x, ctx[i][0]);
                ctx[i][1] = fmaf(p, v0.y, ctx[i][1]);
                ctx[i][2] = fmaf(p, v0.z, ctx[i][2]);
                ctx[i][3] = fmaf(p, v0.w, ctx[i][3]);
                ctx[i][4] = fmaf(p, v1.x, ctx[i][4]);
                ctx[i][5] = fmaf(p, v1.y, ctx[i][5]);
                ctx[i][6] = fmaf(p, v1.z, ctx[i][6]);
                ctx[i][7] = fmaf(p, v1.w, ctx[i][7]);
            }
        }
        __syncthreads();
    }

    // ---- finalize & store ----
#pragma unroll
    for (int i = 0; i < 4; i++) {
        float inv = 1.0f / l_[i];
        int r = q0 + ry * 4 + i;
        float* d = ctxg + (size_t)r * (NH * HD) + h * HD + cx * 4;
        *(float4*)d = make_float4(ctx[i][0] * inv, ctx[i][1] * inv,
                                  ctx[i][2] * inv, ctx[i][3] * inv);
        *(float4*)(d + 64) = make_float4(ctx[i][4] * inv, ctx[i][5] * inv,
                                         ctx[i][6] * inv, ctx[i][7] * inv);
    }
}

// ---------------------------------------------------------------------------
extern "C" void kernel_launch(void* const* d_in, const int* in_sizes, int n_in,
                              void* d_out, int out_size)
{
    (void)in_sizes; (void)n_in; (void)out_size;
    const float* x   = (const float*)d_in[0];
    const float* kdw = (const float*)d_in[1];
    const float* kdb = (const float*)d_in[2];
    const float* kuw = (const float*)d_in[3];
    const float* kub = (const float*)d_in[4];
    const float* vuw = (const float*)d_in[5];
    const float* vub = (const float*)d_in[6];
    const float* krw = (const float*)d_in[7];
    const float* krb = (const float*)d_in[8];
    const float* qdw = (const float*)d_in[9];
    const float* qdb = (const float*)d_in[10];
    const float* quw = (const float*)d_in[11];
    const float* qub = (const float*)d_in[12];
    const float* qrw = (const float*)d_in[13];
    const float* qrb = (const float*)d_in[14];
    const float* ow  = (const float*)d_in[15];
    const float* ob  = (const float*)d_in[16];
    float* out = (float*)d_out;

    float *kvc, *qc, *Kb, *Qb, *Vb, *ctx;
    cudaGetSymbolAddress((void**)&kvc, g_kvc);
    cudaGetSymbolAddress((void**)&qc,  g_qc);
    cudaGetSymbolAddress((void**)&Kb,  g_K);
    cudaGetSymbolAddress((void**)&Qb,  g_Q);
    cudaGetSymbolAddress((void**)&Vb,  g_V);
    cudaGetSymbolAddress((void**)&ctx, g_ctx);

    dim3 blk(256);

    // kv_c = x @ kv_down^T
    gemm_nt<0><<<dim3(KVC / 128, SEQ / 128), blk>>>(x, kdw, kdb, kvc, KVC, HID);
    // q_c = x @ query_down^T
    gemm_nt<0><<<dim3(QC / 128, SEQ / 128), blk>>>(x, qdw, qdb, qc, QC, HID);
    // keys_c -> K[:, :, 0:128]
    gemm_nt<1><<<dim3(2048 / 128, SEQ / 128), blk>>>(kvc, kuw, kub, Kb, 2048, KVC);
    // values -> V
    gemm_nt<0><<<dim3(2048 / 128, SEQ / 128), blk>>>(kvc, vuw, vub, Vb, 2048, KVC);
    // keys_r (+RoPE) -> K[:, :, 128:192]
    gemm_nt<2><<<dim3(1024 / 128, SEQ / 128), blk>>>(kvc, krw, krb, Kb, 1024, KVC);
    // queries_c -> Q[:, :, 0:128]
    gemm_nt<1><<<dim3(2048 / 128, SEQ / 128), blk>>>(qc, quw, qub, Qb, 2048, QC);
    // queries_r (+RoPE) -> Q[:, :, 128:192]
    gemm_nt<2><<<dim3(1024 / 128, SEQ / 128), blk>>>(qc, qrw, qrb, Qb, 1024, QC);

    // attention
    cudaFuncSetAttribute(attn_kernel, cudaFuncAttributeMaxDynamicSharedMemorySize,
                         ATT_SM_BYTES);
    attn_kernel<<<dim3(SEQ / 64, NH), blk, ATT_SM_BYTES>>>(Qb, Kb, Vb, ctx);

    // out = ctx @ out_w^T + out_b
    gemm_nt<0><<<dim3(2048 / 128, SEQ / 128), blk>>>(ctx, ow, ob, out, HID, 2048);
}

// round 2
// speedup vs baseline: 2.5091x; 2.5091x over previous
#include <cuda_runtime.h>
#include <math.h>

#define SEQ  2048
#define HID  2048
#define NH   16
#define HD   128
#define RD   64
#define DT   192        // HD + RD
#define KVC  512
#define QC   1024

// ---------------- scratch (device globals: allocation-free) ----------------
__device__ float g_kvc[SEQ * KVC];
__device__ float g_qc [SEQ * QC];
__device__ float g_K  [SEQ * NH * DT];
__device__ float g_Q  [SEQ * NH * DT];
__device__ float g_V  [SEQ * NH * HD];
__device__ float g_ctx[SEQ * NH * HD];

// ---------------- tf32 helpers ----------------
__device__ __forceinline__ float f2tf(float x) {
    unsigned r;
    asm("cvt.rna.tf32.f32 %0, %1;" : "=r"(r) : "f"(x));
    return __uint_as_float(r);
}

__device__ __forceinline__ void mma_tf32(float* c, const unsigned* a, const unsigned* b) {
    asm volatile(
        "mma.sync.aligned.m16n8k8.row.col.f32.tf32.tf32.f32 "
        "{%0,%1,%2,%3}, {%4,%5,%6,%7}, {%8,%9}, {%0,%1,%2,%3};\n"
        : "+f"(c[0]), "+f"(c[1]), "+f"(c[2]), "+f"(c[3])
        : "r"(a[0]), "r"(a[1]), "r"(a[2]), "r"(a[3]),
          "r"(b[0]), "r"(b[1]));
}

// ---------------------------------------------------------------------------
// Tensor-core GEMM: C[M,N] = A[M,K] @ B[N,K]^T + bias (row-major, K contig).
// 128x128 CTA tile, 4 warps (64x64 each), KT=16, tf32 mma m16n8k8.
// EPI: 0 plain, 1 split [s][h][192]@0 (N=2048), 2 RoPE [s][h][192]@128 (N=1024)
// ---------------------------------------------------------------------------
template<int EPI>
__global__ void __launch_bounds__(128)
gemm_tc(const float* __restrict__ A, const float* __restrict__ B,
        const float* __restrict__ bias, float* __restrict__ C,
        int N, int K)
{
    __shared__ float As[128][20];
    __shared__ float Bs[128][20];

    const int tid  = threadIdx.x;
    const int warp = tid >> 5, lane = tid & 31;
    const int g    = lane >> 2, tig = lane & 3;
    const int wm   = warp >> 1, wn  = warp & 1;
    const int bm   = blockIdx.y * 128, bn = blockIdx.x * 128;

    const float* Ap = A + (size_t)(bm + tid) * K;
    const float* Bp = B + (size_t)(bn + tid) * K;

    float4 av[4], bv[4];
#pragma unroll
    for (int q = 0; q < 4; q++) {
        av[q] = *(const float4*)(Ap + q * 4);
        bv[q] = *(const float4*)(Bp + q * 4);
    }

    float acc[4][8][4];
#pragma unroll
    for (int mi = 0; mi < 4; mi++)
#pragma unroll
        for (int ni = 0; ni < 8; ni++)
#pragma unroll
            for (int e = 0; e < 4; e++) acc[mi][ni][e] = 0.f;

    for (int k0 = 0; k0 < K; k0 += 16) {
#pragma unroll
        for (int q = 0; q < 4; q++) {
            float4 a4 = make_float4(f2tf(av[q].x), f2tf(av[q].y), f2tf(av[q].z), f2tf(av[q].w));
            float4 b4 = make_float4(f2tf(bv[q].x), f2tf(bv[q].y), f2tf(bv[q].z), f2tf(bv[q].w));
            *(float4*)&As[tid][q * 4] = a4;
            *(float4*)&Bs[tid][q * 4] = b4;
        }
        __syncthreads();
        if (k0 + 16 < K) {
#pragma unroll
            for (int q = 0; q < 4; q++) {
                av[q] = *(const float4*)(Ap + k0 + 16 + q * 4);
                bv[q] = *(const float4*)(Bp + k0 + 16 + q * 4);
            }
        }
#pragma unroll
        for (int ks = 0; ks < 2; ks++) {
            unsigned afr[4][4], bfr[8][2];
#pragma unroll
            for (int mi = 0; mi < 4; mi++) {
                int r = wm * 64 + mi * 16 + g;
                afr[mi][0] = __float_as_uint(As[r][ks * 8 + tig]);
                afr[mi][1] = __float_as_uint(As[r + 8][ks * 8 + tig]);
                afr[mi][2] = __float_as_uint(As[r][ks * 8 + tig + 4]);
                afr[mi][3] = __float_as_uint(As[r + 8][ks * 8 + tig + 4]);
            }
#pragma unroll
            for (int ni = 0; ni < 8; ni++) {
                int cI = wn * 64 + ni * 8 + g;
                bfr[ni][0] = __float_as_uint(Bs[cI][ks * 8 + tig]);
                bfr[ni][1] = __float_as_uint(Bs[cI][ks * 8 + tig + 4]);
            }
#pragma unroll
            for (int mi = 0; mi < 4; mi++)
#pragma unroll
                for (int ni = 0; ni < 8; ni++)
                    mma_tf32(acc[mi][ni], afr[mi], bfr[ni]);
        }
        __syncthreads();
    }

    // ---------------- epilogue ----------------
#pragma unroll
    for (int mi = 0; mi < 4; mi++) {
        const int r0 = bm + wm * 64 + mi * 16 + g;
#pragma unroll
        for (int ni = 0; ni < 8; ni++) {
            const int c0 = bn + wn * 64 + ni * 8 + 2 * tig;
            const float b0 = bias[c0], b1 = bias[c0 + 1];
            float v00 = acc[mi][ni][0] + b0, v01 = acc[mi][ni][1] + b1;
            float v10 = acc[mi][ni][2] + b0, v11 = acc[mi][ni][3] + b1;
            if (EPI == 2) {
                const int hh = c0 >> 6;
                const int rr = c0 & 63;
                const int jj = rr >> 1;
                float fr = __expf(-(float)jj * 0.28782313663258307f); // ln(1e4)/32
                float sn, cs;
                sincosf((float)hh * fr, &sn, &cs);
                float w00 = v00 * cs - v01 * sn, w01 = v00 * sn + v01 * cs;
                float w10 = v10 * cs - v11 * sn, w11 = v10 * sn + v11 * cs;
                float* d0 = C + ((size_t)r0 * NH + hh) * DT + HD + rr;
                float* d1 = C + ((size_t)(r0 + 8) * NH + hh) * DT + HD + rr;
                *(float2*)d0 = make_float2(w00, w01);
                *(float2*)d1 = make_float2(w10, w11);
            } else if (EPI == 1) {
                const int hh = c0 >> 7, dd = c0 & 127;
                float* d0 = C + ((size_t)r0 * NH + hh) * DT + dd;
                float* d1 = C + ((size_t)(r0 + 8) * NH + hh) * DT + dd;
                *(float2*)d0 = make_float2(v00, v01);
                *(float2*)d1 = make_float2(v10, v11);
            } else {
                *(float2*)&C[(size_t)r0 * N + c0]       = make_float2(v00, v01);
                *(float2*)&C[(size_t)(r0 + 8) * N + c0] = make_float2(v10, v11);
            }
        }
    }
}

// ---------------------------------------------------------------------------
// Flash attention with tf32 mma. Block = (head, 128 q-rows), 256 threads,
// 8 warps each owning 16 q-rows (full 64-col / 128-col width -> softmax
// reductions stay inside 4-lane quads).
// ---------------------------------------------------------------------------
#define QS_LD 196
#define KS_LD 196
#define VS_LD 136
#define PS_LD 68
#define ATTN_SM_FLOATS (128*QS_LD + 64*KS_LD + 64*VS_LD + 128*PS_LD)
#define ATTN_SM_BYTES  (ATTN_SM_FLOATS * 4)

__global__ void __launch_bounds__(256)
attn_tc(const float* __restrict__ Qg, const float* __restrict__ Kg,
        const float* __restrict__ Vg, float* __restrict__ ctxg)
{
    extern __shared__ float sm[];
    float* Qs = sm;                      // [128][196]
    float* Ks = Qs + 128 * QS_LD;        // [64][196]
    float* Vs = Ks + 64 * KS_LD;         // [64][136]
    float* Ps = Vs + 64 * VS_LD;         // [128][68]

    const int tid  = threadIdx.x;
    const int warp = tid >> 5, lane = tid & 31;
    const int g    = lane >> 2, tig = lane & 3;
    const int h    = blockIdx.y;
    const int q0   = blockIdx.x * 128;

    // ---- load Q tile (cvt to tf32) ----
#pragma unroll
    for (int i = 0; i < 24; i++) {
        int idx = tid + 256 * i;
        int row = idx / 48, f4 = idx % 48;
        const float* p = Qg + (size_t)(q0 + row) * (NH * DT) + h * DT + f4 * 4;
        float4 v = *(const float4*)p;
        *(float4*)&Qs[row * QS_LD + f4 * 4] =
            make_float4(f2tf(v.x), f2tf(v.y), f2tf(v.z), f2tf(v.w));
    }

    float m_[2] = {-1e30f, -1e30f}, l_[2] = {0.f, 0.f};
    float o[16][4];
#pragma unroll
    for (int ni = 0; ni < 16; ni++)
#pragma unroll
        for (int e = 0; e < 4; e++) o[ni][e] = 0.f;

    const float SCALE = 0.07216878364870323f;   // 1/sqrt(192)

    for (int kt = 0; kt < SEQ / 64; kt++) {
        const int kbase = kt * 64;
        // ---- K tile ----
#pragma unroll
        for (int i = 0; i < 12; i++) {
            int idx = tid + 256 * i;
            int row = idx / 48, f4 = idx % 48;
            const float* p = Kg + (size_t)(kbase + row) * (NH * DT) + h * DT + f4 * 4;
            float4 v = *(const float4*)p;
            *(float4*)&Ks[row * KS_LD + f4 * 4] =
                make_float4(f2tf(v.x), f2tf(v.y), f2tf(v.z), f2tf(v.w));
        }
        // ---- V tile ----
#pragma unroll
        for (int i = 0; i < 8; i++) {
            int idx = tid + 256 * i;
            int row = idx >> 5, f4 = idx & 31;
            const float* p = Vg + (size_t)(kbase + row) * (NH * HD) + h * HD + f4 * 4;
            float4 v = *(const float4*)p;
            *(float4*)&Vs[row * VS_LD + f4 * 4] =
                make_float4(f2tf(v.x), f2tf(v.y), f2tf(v.z), f2tf(v.w));
        }
        __syncthreads();

        // ---- S = Q K^T : warp rows = warp*16, cols 0..63 ----
        float s[8][4];
#pragma unroll
        for (int ni = 0; ni < 8; ni++)
#pragma unroll
            for (int e = 0; e < 4; e++) s[ni][e] = 0.f;

        const int rw = warp * 16 + g;
#pragma unroll
        for (int kk = 0; kk < 24; kk++) {
            const int kk8 = kk * 8;
            unsigned a[4];
            a[0] = __float_as_uint(Qs[rw * QS_LD + kk8 + tig]);
            a[1] = __float_as_uint(Qs[(rw + 8) * QS_LD + kk8 + tig]);
            a[2] = __float_as_uint(Qs[rw * QS_LD + kk8 + tig + 4]);
            a[3] = __float_as_uint(Qs[(rw + 8) * QS_LD + kk8 + tig + 4]);
#pragma unroll
            for (int ni = 0; ni < 8; ni++) {
                const int cI = ni * 8 + g;
                unsigned b[2];
                b[0] = __float_as_uint(Ks[cI * KS_LD + kk8 + tig]);
                b[1] = __float_as_uint(Ks[cI * KS_LD + kk8 + tig + 4]);
                mma_tf32(s[ni], a, b);
            }
        }

        // ---- online softmax (rows g / g+8 within warp's 16) ----
        float tm0 = -1e30f, tm1 = -1e30f;
#pragma unroll
        for (int ni = 0; ni < 8; ni++) {
#pragma unroll
            for (int e = 0; e < 4; e++) s[ni][e] *= SCALE;
            tm0 = fmaxf(tm0, fmaxf(s[ni][0], s[ni][1]));
            tm1 = fmaxf(tm1, fmaxf(s[ni][2], s[ni][3]));
        }
        tm0 = fmaxf(tm0, __shfl_xor_sync(0xffffffffu, tm0, 1, 4));
        tm0 = fmaxf(tm0, __shfl_xor_sync(0xffffffffu, tm0, 2, 4));
        tm1 = fmaxf(tm1, __shfl_xor_sync(0xffffffffu, tm1, 1, 4));
        tm1 = fmaxf(tm1, __shfl_xor_sync(0xffffffffu, tm1, 2, 4));

        float mn0 = fmaxf(m_[0], tm0), mn1 = fmaxf(m_[1], tm1);
        float corr0 = __expf(m_[0] - mn0), corr1 = __expf(m_[1] - mn1);
        m_[0] = mn0; m_[1] = mn1;

        float rs0 = 0.f, rs1 = 0.f;
#pragma unroll
        for (int ni = 0; ni < 8; ni++) {
            s[ni][0] = __expf(s[ni][0] - mn0);
            s[ni][1] = __expf(s[ni][1] - mn0);
            s[ni][2] = __expf(s[ni][2] - mn1);
            s[ni][3] = __expf(s[ni][3] - mn1);
            rs0 += s[ni][0] + s[ni][1];
            rs1 += s[ni][2] + s[ni][3];
        }
        rs0 += __shfl_xor_sync(0xffffffffu, rs0, 1, 4);
        rs0 += __shfl_xor_sync(0xffffffffu, rs0, 2, 4);
        rs1 += __shfl_xor_sync(0xffffffffu, rs1, 1, 4);
        rs1 += __shfl_xor_sync(0xffffffffu, rs1, 2, 4);
        l_[0] = l_[0] * corr0 + rs0;
        l_[1] = l_[1] * corr1 + rs1;

        // ---- stage P (tf32), rescale ctx ----
#pragma unroll
        for (int ni = 0; ni < 8; ni++) {
            *(float2*)&Ps[rw * PS_LD + ni * 8 + 2 * tig] =
                make_float2(f2tf(s[ni][0]), f2tf(s[ni][1]));
            *(float2*)&Ps[(rw + 8) * PS_LD + ni * 8 + 2 * tig] =
                make_float2(f2tf(s[ni][2]), f2tf(s[ni][3]));
        }
#pragma unroll
        for (int ni = 0; ni < 16; ni++) {
            o[ni][0] *= corr0; o[ni][1] *= corr0;
            o[ni][2] *= corr1; o[ni][3] *= corr1;
        }
        __syncthreads();

        // ---- ctx += P @ V ----
#pragma unroll
        for (int kk = 0; kk < 8; kk++) {
            const int kk8 = kk * 8;
            unsigned a[4];
            a[0] = __float_as_uint(Ps[rw * PS_LD + kk8 + tig]);
            a[1] = __float_as_uint(Ps[(rw + 8) * PS_LD + kk8 + tig]);
            a[2] = __float_as_uint(Ps[rw * PS_LD + kk8 + tig + 4]);
            a[3] = __float_as_uint(Ps[(rw + 8) * PS_LD + kk8 + tig + 4]);
#pragma unroll
            for (int ni = 0; ni < 16; ni++) {
                unsigned b[2];
                b[0] = __float_as_uint(Vs[(kk8 + tig) * VS_LD + ni * 8 + g]);
                b[1] = __float_as_uint(Vs[(kk8 + tig + 4) * VS_LD + ni * 8 + g]);
                mma_tf32(o[ni], a, b);
            }
        }
        __syncthreads();
    }

    // ---- finalize & store ----
    const float inv0 = 1.0f / l_[0], inv1 = 1.0f / l_[1];
    const int r0 = q0 + warp * 16 + g;
#pragma unroll
    for (int ni = 0; ni < 16; ni++) {
        const int col = ni * 8 + 2 * tig;
        *(float2*)&ctxg[(size_t)r0 * (NH * HD) + h * HD + col] =
            make_float2(o[ni][0] * inv0, o[ni][1] * inv0);
        *(float2*)&ctxg[(size_t)(r0 + 8) * (NH * HD) + h * HD + col] =
            make_float2(o[ni][2] * inv1, o[ni][3] * inv1);
    }
}

// ---------------------------------------------------------------------------
extern "C" void kernel_launch(void* const* d_in, const int* in_sizes, int n_in,
                              void* d_out, int out_size)
{
    (void)in_sizes; (void)n_in; (void)out_size;
    const float* x   = (const float*)d_in[0];
    const float* kdw = (const float*)d_in[1];
    const float* kdb = (const float*)d_in[2];
    const float* kuw = (const float*)d_in[3];
    const float* kub = (const float*)d_in[4];
    const float* vuw = (const float*)d_in[5];
    const float* vub = (const float*)d_in[6];
    const float* krw = (const float*)d_in[7];
    const float* krb = (const float*)d_in[8];
    const float* qdw = (const float*)d_in[9];
    const float* qdb = (const float*)d_in[10];
    const float* quw = (const float*)d_in[11];
    const float* qub = (const float*)d_in[12];
    const float* qrw = (const float*)d_in[13];
    const float* qrb = (const float*)d_in[14];
    const float* ow  = (const float*)d_in[15];
    const float* ob  = (const float*)d_in[16];
    float* out = (float*)d_out;

    float *kvc, *qc, *Kb, *Qb, *Vb, *ctx;
    cudaGetSymbolAddress((void**)&kvc, g_kvc);
    cudaGetSymbolAddress((void**)&qc,  g_qc);
    cudaGetSymbolAddress((void**)&Kb,  g_K);
    cudaGetSymbolAddress((void**)&Qb,  g_Q);
    cudaGetSymbolAddress((void**)&Vb,  g_V);
    cudaGetSymbolAddress((void**)&ctx, g_ctx);

    dim3 blk(128);

    gemm_tc<0><<<dim3(KVC / 128, SEQ / 128), blk>>>(x, kdw, kdb, kvc, KVC, HID);
    gemm_tc<0><<<dim3(QC / 128, SEQ / 128), blk>>>(x, qdw, qdb, qc, QC, HID);
    gemm_tc<1><<<dim3(2048 / 128, SEQ / 128), blk>>>(kvc, kuw, kub, Kb, 2048, KVC);
    gemm_tc<0><<<dim3(2048 / 128, SEQ / 128), blk>>>(kvc, vuw, vub, Vb, 2048, KVC);
    gemm_tc<2><<<dim3(1024 / 128, SEQ / 128), blk>>>(kvc, krw, krb, Kb, 1024, KVC);
    gemm_tc<1><<<dim3(2048 / 128, SEQ / 128), blk>>>(qc, quw, qub, Qb, 2048, QC);
    gemm_tc<2><<<dim3(1024 / 128, SEQ / 128), blk>>>(qc, qrw, qrb, Qb, 1024, QC);

    cudaFuncSetAttribute(attn_tc, cudaFuncAttributeMaxDynamicSharedMemorySize,
                         ATTN_SM_BYTES);
    attn_tc<<<dim3(SEQ / 128, NH), dim3(256), ATTN_SM_BYTES>>>(Qb, Kb, Vb, ctx);

    gemm_tc<0><<<dim3(2048 / 128, SEQ / 128), blk>>>(ctx, ow, ob, out, HID, 2048);
}

// round 4
// speedup vs baseline: 2.7622x; 1.1009x over previous
#include <cuda_runtime.h>
#include <math.h>

#define SEQ  2048
#define HID  2048
#define NH   16
#define HD   128
#define RD   64
#define DT   192        // HD + RD
#define KVC  512
#define QC   1024

// ---------------- scratch (device globals: allocation-free) ----------------
__device__ float g_kvc[SEQ * KVC];
__device__ float g_qc [SEQ * QC];
__device__ float g_K  [SEQ * NH * DT];
__device__ float g_Q  [SEQ * NH * DT];
__device__ float g_V  [SEQ * NH * HD];
__device__ float g_ctx[SEQ * NH * HD];

// ---------------- helpers ----------------
__device__ __forceinline__ float f2tf(float x) {
    unsigned r;
    asm("cvt.rna.tf32.f32 %0, %1;" : "=r"(r) : "f"(x));
    return __uint_as_float(r);
}
__device__ __forceinline__ unsigned cvtu(unsigned x) {
    unsigned r;
    asm("cvt.rna.tf32.f32 %0, %1;" : "=r"(r) : "f"(__uint_as_float(x)));
    return r;
}

__device__ __forceinline__ void mma_tf32(float* c, const unsigned* a, const unsigned* b) {
    asm volatile(
        "mma.sync.aligned.m16n8k8.row.col.f32.tf32.tf32.f32 "
        "{%0,%1,%2,%3}, {%4,%5,%6,%7}, {%8,%9}, {%0,%1,%2,%3};\n"
        : "+f"(c[0]), "+f"(c[1]), "+f"(c[2]), "+f"(c[3])
        : "r"(a[0]), "r"(a[1]), "r"(a[2]), "r"(a[3]),
          "r"(b[0]), "r"(b[1]));
}

__device__ __forceinline__ void ldsm4(unsigned* r, const void* p) {
    unsigned addr = (unsigned)__cvta_generic_to_shared(p);
    asm volatile("ldmatrix.sync.aligned.m8n8.x4.shared.b16 {%0,%1,%2,%3}, [%4];"
        : "=r"(r[0]), "=r"(r[1]), "=r"(r[2]), "=r"(r[3]) : "r"(addr));
}

// ---------------------------------------------------------------------------
// Tensor-core GEMM: C[M,N] = A[M,K] @ B[N,K]^T + bias (row-major, K contig).
// 128x128 CTA, 256 threads, 8 warps (warp tile 32x64), KT=16, ldmatrix frags.
// EPI: 0 plain, 1 split [s][h][192]@0, 2 RoPE [s][h][192]@128
// RND: round outputs to tf32 (for intermediates consumed by later mma).
// ---------------------------------------------------------------------------
template<int EPI, bool RND>
__global__ void __launch_bounds__(256, 2)
gemm_tc(const float* __restrict__ A, const float* __restrict__ B,
        const float* __restrict__ bias, float* __restrict__ C,
        int N, int K)
{
    __shared__ float As[128][20];
    __shared__ float Bs[128][20];

    const int tid  = threadIdx.x;
    const int warp = tid >> 5, lane = tid & 31;
    const int g    = lane >> 2, tig = lane & 3;
    const int wm   = warp >> 1, wn  = warp & 1;      // wm 0..3 (32 rows), wn 0..1 (64 cols)
    const int bm   = blockIdx.y * 128, bn = blockIdx.x * 128;

    // loader: threads 0..127 own A row, 128..255 own B row; 4 float4 each (k0..15)
    const int lrow = tid & 127;
    const float* src = (tid < 128) ? (A + (size_t)(bm + lrow) * K)
                                   : (B + (size_t)(bn + lrow) * K);
    float* dstrow = (tid < 128) ? &As[lrow][0] : &Bs[lrow][0];

    float4 st[4];
#pragma unroll
    for (int q = 0; q < 4; q++) st[q] = *(const float4*)(src + q * 4);

    float acc[2][8][4];
#pragma unroll
    for (int mi = 0; mi < 2; mi++)
#pragma unroll
        for (int ni = 0; ni < 8; ni++)
#pragma unroll
            for (int e = 0; e < 4; e++) acc[mi][ni][e] = 0.f;

    // ldmatrix lane addressing (precomputed pieces)
    const int a_row = (lane & 15);            // row within m16 tile
    const int a_k   = 4 * (lane >> 4);        // +0 / +4
    const int b_row = ((lane >> 4) << 3) + (lane & 7);   // row within n16 pair
    const int b_k   = 4 * ((lane >> 3) & 1);

    for (int k0 = 0; k0 < K; k0 += 16) {
#pragma unroll
        for (int q = 0; q < 4; q++) *(float4*)(dstrow + q * 4) = st[q];
        __syncthreads();
        if (k0 + 16 < K) {
#pragma unroll
            for (int q = 0; q < 4; q++)
                st[q] = *(const float4*)(src + k0 + 16 + q * 4);
        }
#pragma unroll
        for (int ks = 0; ks < 2; ks++) {
            const int k8 = ks * 8;
            unsigned a[2][4];
#pragma unroll
            for (int mi = 0; mi < 2; mi++) {
                ldsm4(a[mi], &As[wm * 32 + mi * 16 + a_row][k8 + a_k]);
#pragma unroll
                for (int e = 0; e < 4; e++) a[mi][e] = cvtu(a[mi][e]);
            }
            unsigned b[8][2];
#pragma unroll
            for (int nip = 0; nip < 4; nip++) {
                unsigned t4[4];
                ldsm4(t4, &Bs[wn * 64 + nip * 16 + b_row][k8 + b_k]);
                b[2 * nip][0]     = cvtu(t4[0]);
                b[2 * nip][1]     = cvtu(t4[1]);
                b[2 * nip + 1][0] = cvtu(t4[2]);
                b[2 * nip + 1][1] = cvtu(t4[3]);
            }
#pragma unroll
            for (int mi = 0; mi < 2; mi++)
#pragma unroll
                for (int ni = 0; ni < 8; ni++)
                    mma_tf32(acc[mi][ni], a[mi], b[ni]);
        }
        __syncthreads();
    }

    // ---------------- epilogue ----------------
#pragma unroll
    for (int mi = 0; mi < 2; mi++) {
        const int r0 = bm + wm * 32 + mi * 16 + g;
#pragma unroll
        for (int ni = 0; ni < 8; ni++) {
            const int c0 = bn + wn * 64 + ni * 8 + 2 * tig;
            const float b0 = bias[c0], b1 = bias[c0 + 1];
            float v00 = acc[mi][ni][0] + b0, v01 = acc[mi][ni][1] + b1;
            float v10 = acc[mi][ni][2] + b0, v11 = acc[mi][ni][3] + b1;
            if (EPI == 2) {
                const int hh = c0 >> 6;
                const int rr = c0 & 63;
                const int jj = rr >> 1;
                float fr = __expf(-(float)jj * 0.28782313663258307f); // ln(1e4)/32
                float sn, cs;
                sincosf((float)hh * fr, &sn, &cs);
                float w00 = v00 * cs - v01 * sn, w01 = v00 * sn + v01 * cs;
                float w10 = v10 * cs - v11 * sn, w11 = v10 * sn + v11 * cs;
                if (RND) { w00 = f2tf(w00); w01 = f2tf(w01); w10 = f2tf(w10); w11 = f2tf(w11); }
                float* d0 = C + ((size_t)r0 * NH + hh) * DT + HD + rr;
                float* d1 = C + ((size_t)(r0 + 8) * NH + hh) * DT + HD + rr;
                *(float2*)d0 = make_float2(w00, w01);
                *(float2*)d1 = make_float2(w10, w11);
            } else {
                if (RND) { v00 = f2tf(v00); v01 = f2tf(v01); v10 = f2tf(v10); v11 = f2tf(v11); }
                if (EPI == 1) {
                    const int hh = c0 >> 7, dd = c0 & 127;
                    float* d0 = C + ((size_t)r0 * NH + hh) * DT + dd;
                    float* d1 = C + ((size_t)(r0 + 8) * NH + hh) * DT + dd;
                    *(float2*)d0 = make_float2(v00, v01);
                    *(float2*)d1 = make_float2(v10, v11);
                } else {
                    *(float2*)&C[(size_t)r0 * N + c0]       = make_float2(v00, v01);
                    *(float2*)&C[(size_t)(r0 + 8) * N + c0] = make_float2(v10, v11);
                }
            }
        }
    }
}

// ---------------------------------------------------------------------------
// Flash attention, tf32 mma + ldmatrix. Block = (head, 128 q-rows), 256 thr.
// Q/K/V pre-rounded to tf32 by producer epilogues (no cvt here).
// V transposed into smem with XOR swizzle for ldmatrix B-fragments.
// ---------------------------------------------------------------------------
#define QS_LD 196
#define KS_LD 196
#define VLD   68
#define PS_LD 68
#define ATTN_SM_FLOATS (128*QS_LD + 64*KS_LD + 128*VLD + 128*PS_LD)
#define ATTN_SM_BYTES  (ATTN_SM_FLOATS * 4)

__device__ __forceinline__ int vst_off(int d, int k) {
    return d * VLD + ((((k >> 2) ^ ((d >> 3) & 7))) << 2) + (k & 3);
}

__global__ void __launch_bounds__(256)
attn_tc(const float* __restrict__ Qg, const float* __restrict__ Kg,
        const float* __restrict__ Vg, float* __restrict__ ctxg)
{
    extern __shared__ float sm[];
    float* Qs  = sm;                       // [128][196]
    float* Ks  = Qs + 128 * QS_LD;         // [64][196]
    float* Vst = Ks + 64 * KS_LD;          // [128][68]  (d-major, swizzled k)
    float* Ps  = Vst + 128 * VLD;          // [128][68]

    const int tid  = threadIdx.x;
    const int warp = tid >> 5, lane = tid & 31;
    const int g    = lane >> 2, tig = lane & 3;
    const int h    = blockIdx.y;
    const int q0   = blockIdx.x * 128;

    const int a_row = (lane & 15);
    const int a_k   = 4 * (lane >> 4);
    const int b_row = ((lane >> 4) << 3) + (lane & 7);
    const int b_k   = 4 * ((lane >> 3) & 1);
    const int b_ks  = (lane >> 3) & 1;     // k8-half select for swizzled V

    // ---- load Q tile (raw copy; already tf32) ----
#pragma unroll
    for (int i = 0; i < 24; i++) {
        int idx = tid + 256 * i;
        int row = idx / 48, f4 = idx % 48;
        *(float4*)&Qs[row * QS_LD + f4 * 4] =
            *(const float4*)(Qg + (size_t)(q0 + row) * (NH * DT) + h * DT + f4 * 4);
    }

    float m_[2] = {-1e30f, -1e30f}, l_[2] = {0.f, 0.f};
    float o[16][4];
#pragma unroll
    for (int ni = 0; ni < 16; ni++)
#pragma unroll
        for (int e = 0; e < 4; e++) o[ni][e] = 0.f;

    const float SCALE = 0.07216878364870323f;   // 1/sqrt(192)
    const int rw = warp * 16;
    const int prow = rw + g;

    for (int kt = 0; kt < SEQ / 64; kt++) {
        const int kbase = kt * 64;
        // ---- K tile ----
#pragma unroll
        for (int i = 0; i < 12; i++) {
            int idx = tid + 256 * i;
            int row = idx / 48, f4 = idx % 48;
            *(float4*)&Ks[row * KS_LD + f4 * 4] =
                *(const float4*)(Kg + (size_t)(kbase + row) * (NH * DT) + h * DT + f4 * 4);
        }
        // ---- V tile, transposed with swizzle ----
#pragma unroll
        for (int i = 0; i < 8; i++) {
            int idx = tid + 256 * i;
            int krow = idx >> 5, d4 = (idx & 31) << 2;
            float4 v = *(const float4*)(Vg + (size_t)(kbase + krow) * (NH * HD) + h * HD + d4);
            Vst[vst_off(d4 + 0, krow)] = v.x;
            Vst[vst_off(d4 + 1, krow)] = v.y;
            Vst[vst_off(d4 + 2, krow)] = v.z;
            Vst[vst_off(d4 + 3, krow)] = v.w;
        }
        __syncthreads();

        // ---- S = Q K^T : warp rows rw..rw+15, cols 0..63 ----
        float s[8][4];
#pragma unroll
        for (int ni = 0; ni < 8; ni++)
#pragma unroll
            for (int e = 0; e < 4; e++) s[ni][e] = 0.f;

#pragma unroll
        for (int kk = 0; kk < 24; kk++) {
            const int k8 = kk * 8;
            unsigned a[4];
            ldsm4(a, &Qs[(rw + a_row) * QS_LD + k8 + a_k]);
#pragma unroll
            for (int nip = 0; nip < 4; nip++) {
                unsigned b[4];
                ldsm4(b, &Ks[(nip * 16 + b_row) * KS_LD + k8 + b_k]);
                mma_tf32(s[2 * nip], a, b);
                mma_tf32(s[2 * nip + 1], a, b + 2);
            }
        }

        // ---- online softmax (rows prow / prow+8) ----
        float tm0 = -1e30f, tm1 = -1e30f;
#pragma unroll
        for (int ni = 0; ni < 8; ni++) {
#pragma unroll
            for (int e = 0; e < 4; e++) s[ni][e] *= SCALE;
            tm0 = fmaxf(tm0, fmaxf(s[ni][0], s[ni][1]));
            tm1 = fmaxf(tm1, fmaxf(s[ni][2], s[ni][3]));
        }
        tm0 = fmaxf(tm0, __shfl_xor_sync(0xffffffffu, tm0, 1, 4));
        tm0 = fmaxf(tm0, __shfl_xor_sync(0xffffffffu, tm0, 2, 4));
        tm1 = fmaxf(tm1, __shfl_xor_sync(0xffffffffu, tm1, 1, 4));
        tm1 = fmaxf(tm1, __shfl_xor_sync(0xffffffffu, tm1, 2, 4));

        float mn0 = fmaxf(m_[0], tm0), mn1 = fmaxf(m_[1], tm1);
        float corr0 = __expf(m_[0] - mn0), corr1 = __expf(m_[1] - mn1);
        m_[0] = mn0; m_[1] = mn1;

        float rs0 = 0.f, rs1 = 0.f;
#pragma unroll
        for (int ni = 0; ni < 8; ni++) {
            s[ni][0] = __expf(s[ni][0] - mn0);
            s[ni][1] = __expf(s[ni][1] - mn0);
            s[ni][2] = __expf(s[ni][2] - mn1);
            s[ni][3] = __expf(s[ni][3] - mn1);
            rs0 += s[ni][0] + s[ni][1];
            rs1 += s[ni][2] + s[ni][3];
        }
        rs0 += __shfl_xor_sync(0xffffffffu, rs0, 1, 4);
        rs0 += __shfl_xor_sync(0xffffffffu, rs0, 2, 4);
        rs1 += __shfl_xor_sync(0xffffffffu, rs1, 1, 4);
        rs1 += __shfl_xor_sync(0xffffffffu, rs1, 2, 4);
        l_[0] = l_[0] * corr0 + rs0;
        l_[1] = l_[1] * corr1 + rs1;

        // ---- stage P (tf32, warp-local rows), rescale ctx ----
#pragma unroll
        for (int ni = 0; ni < 8; ni++) {
            *(float2*)&Ps[prow * PS_LD + ni * 8 + 2 * tig] =
                make_float2(f2tf(s[ni][0]), f2tf(s[ni][1]));
            *(float2*)&Ps[(prow + 8) * PS_LD + ni * 8 + 2 * tig] =
                make_float2(f2tf(s[ni][2]), f2tf(s[ni][3]));
        }
#pragma unroll
        for (int ni = 0; ni < 16; ni++) {
            o[ni][0] *= corr0; o[ni][1] *= corr0;
            o[ni][2] *= corr1; o[ni][3] *= corr1;
        }
        __syncwarp();

        // ---- ctx += P @ V (A from Ps, B from swizzled Vst) ----
#pragma unroll
        for (int ks = 0; ks < 8; ks++) {
            unsigned a[4];
            ldsm4(a, &Ps[(rw + a_row) * PS_LD + ks * 8 + a_k]);
#pragma unroll
            for (int nip = 0; nip < 8; nip++) {
                const int d = nip * 16 + b_row;
                const int kunit = 2 * ks + b_ks;
                unsigned b[4];
                ldsm4(b, &Vst[d * VLD + (((kunit ^ ((d >> 3) & 7))) << 2)]);
                mma_tf32(o[2 * nip], a, b);
                mma_tf32(o[2 * nip + 1], a, b + 2);
            }
        }
        __syncthreads();
    }

    // ---- finalize & store (raw fp32; consumer GEMM rounds) ----
    const float inv0 = 1.0f / l_[0], inv1 = 1.0f / l_[1];
    const int r0 = q0 + rw + g;
#pragma unroll
    for (int ni = 0; ni < 16; ni++) {
        const int col = ni * 8 + 2 * tig;
        *(float2*)&ctxg[(size_t)r0 * (NH * HD) + h * HD + col] =
            make_float2(o[ni][0] * inv0, o[ni][1] * inv0);
        *(float2*)&ctxg[(size_t)(r0 + 8) * (NH * HD) + h * HD + col] =
            make_float2(o[ni][2] * inv1, o[ni][3] * inv1);
    }
}

// ---------------------------------------------------------------------------
extern "C" void kernel_launch(void* const* d_in, const int* in_sizes, int n_in,
                              void* d_out, int out_size)
{
    (void)in_sizes; (void)n_in; (void)out_size;
    const float* x   = (const float*)d_in[0];
    const float* kdw = (const float*)d_in[1];
    const float* kdb = (const float*)d_in[2];
    const float* kuw = (const float*)d_in[3];
    const float* kub = (const float*)d_in[4];
    const float* vuw = (const float*)d_in[5];
    const float* vub = (const float*)d_in[6];
    const float* krw = (const float*)d_in[7];
    const float* krb = (const float*)d_in[8];
    const float* qdw = (const float*)d_in[9];
    const float* qdb = (const float*)d_in[10];
    const float* quw = (const float*)d_in[11];
    const float* qub = (const float*)d_in[12];
    const float* qrw = (const float*)d_in[13];
    const float* qrb = (const float*)d_in[14];
    const float* ow  = (const float*)d_in[15];
    const float* ob  = (const float*)d_in[16];
    float* out = (float*)d_out;

    float *kvc, *qc, *Kb, *Qb, *Vb, *ctx;
    cudaGetSymbolAddress((void**)&kvc, g_kvc);
    cudaGetSymbolAddress((void**)&qc,  g_qc);
    cudaGetSymbolAddress((void**)&Kb,  g_K);
    cudaGetSymbolAddress((void**)&Qb,  g_Q);
    cudaGetSymbolAddress((void**)&Vb,  g_V);
    cudaGetSymbolAddress((void**)&ctx, g_ctx);

    dim3 blk(256);

    gemm_tc<0, true ><<<dim3(KVC / 128, SEQ / 128), blk>>>(x, kdw, kdb, kvc, KVC, HID);
    gemm_tc<0, true ><<<dim3(QC / 128, SEQ / 128), blk>>>(x, qdw, qdb, qc, QC, HID);
    gemm_tc<1, true ><<<dim3(2048 / 128, SEQ / 128), blk>>>(kvc, kuw, kub, Kb, 2048, KVC);
    gemm_tc<0, true ><<<dim3(2048 / 128, SEQ / 128), blk>>>(kvc, vuw, vub, Vb, 2048, KVC);
    gemm_tc<2, true ><<<dim3(1024 / 128, SEQ / 128), blk>>>(kvc, krw, krb, Kb, 1024, KVC);
    gemm_tc<1, true ><<<dim3(2048 / 128, SEQ / 128), blk>>>(qc, quw, qub, Qb, 2048, QC);
    gemm_tc<2, true ><<<dim3(1024 / 128, SEQ / 128), blk>>>(qc, qrw, qrb, Qb, 1024, QC);

    cudaFuncSetAttribute(attn_tc, cudaFuncAttributeMaxDynamicSharedMemorySize,
                         ATTN_SM_BYTES);
    attn_tc<<<dim3(SEQ / 128, NH), dim3(256), ATTN_SM_BYTES>>>(Qb, Kb, Vb, ctx);

    gemm_tc<0, false><<<dim3(2048 / 128, SEQ / 128), blk>>>(ctx, ow, ob, out, HID, 2048);
}